// round 1
// baseline (speedup 1.0000x reference)
#include <cuda_runtime.h>

#define BB 2
#define TT 4096
#define CC 768
#define NH 12
#define HD 64
#define C3 (3*CC)

// Scratch (no cudaMalloc allowed)
__device__ float g_qkv[BB*TT*C3];   // [B,T,3C] : (k | q | v)
__device__ float g_att[BB*TT*CC];   // attention output before proj

// ---------------------------------------------------------------------------
// GEMM: out[M,N] = A[M,K] @ W[K,N] + bias[N]
// 64x64 block tile, BK=16, 256 threads, 4x4 per thread, float4 smem reads.
// M,N divisible by 64; K divisible by 16 (holds for all our shapes).
// ---------------------------------------------------------------------------
__global__ void gemm_bias_kernel(const float* __restrict__ A,
                                 const float* __restrict__ W,
                                 const float* __restrict__ bias,
                                 float* __restrict__ out,
                                 int M, int N, int K) {
    __shared__ float As[16][68];   // [k][m]
    __shared__ float Bs[16][68];   // [k][n]
    const int tid = threadIdx.x;
    const int tx = tid & 15, ty = tid >> 4;
    const int n0 = blockIdx.x * 64;
    const int m0 = blockIdx.y * 64;

    float acc[4][4] = {};

    for (int k0 = 0; k0 < K; k0 += 16) {
        // A tile 64x16 -> As[k][m]
        #pragma unroll
        for (int i = 0; i < 4; i++) {
            int e = tid + i * 256;
            int m = e >> 4, k = e & 15;
            As[k][m] = A[(size_t)(m0 + m) * K + k0 + k];
        }
        // W tile 16x64 -> Bs[k][n]
        #pragma unroll
        for (int i = 0; i < 4; i++) {
            int e = tid + i * 256;
            int k = e >> 6, n = e & 63;
            Bs[k][n] = W[(size_t)(k0 + k) * N + n0 + n];
        }
        __syncthreads();
        #pragma unroll
        for (int kk = 0; kk < 16; kk++) {
            float4 a4 = *(const float4*)&As[kk][ty * 4];
            float4 b4 = *(const float4*)&Bs[kk][tx * 4];
            float a[4] = {a4.x, a4.y, a4.z, a4.w};
            float b[4] = {b4.x, b4.y, b4.z, b4.w};
            #pragma unroll
            for (int i = 0; i < 4; i++)
                #pragma unroll
                for (int j = 0; j < 4; j++)
                    acc[i][j] += a[i] * b[j];
        }
        __syncthreads();
    }

    #pragma unroll
    for (int i = 0; i < 4; i++) {
        int m = m0 + ty * 4 + i;
        #pragma unroll
        for (int j = 0; j < 4; j++) {
            int n = n0 + tx * 4 + j;
            out[(size_t)m * N + n] = acc[i][j] + bias[n];
        }
    }
}

// ---------------------------------------------------------------------------
// Flash attention (causal), fp32, online softmax.
// grid: (T/64 q-tiles, B*H). block: 256 threads (16x16), each thread owns a
// 4x4 patch of the 64x64 S tile and a 4x4 patch of the 64x64 O tile.
// V is stored transposed in smem so P@V uses contiguous float4 dots.
// ---------------------------------------------------------------------------
#define PAD 68
__global__ void flash_attn_kernel(const float* __restrict__ qkv,
                                  float* __restrict__ att) {
    extern __shared__ float sm[];
    float* Qs  = sm;                 // [64][PAD]
    float* Ks  = sm + 64 * PAD;      // [64][PAD]
    float* Vt  = sm + 2 * 64 * PAD;  // [64(d)][PAD(c)]
    float* Ps  = sm + 3 * 64 * PAD;  // [64][PAD]
    float* red = sm + 4 * 64 * PAD;  // [64][17]

    const int tid = threadIdx.x;
    const int tx = tid & 15, ty = tid >> 4;
    const int qt = blockIdx.x;
    const int bh = blockIdx.y;
    const int b = bh / NH, h = bh % NH;
    const float scale = 0.125f;  // 1/sqrt(64)

    const float* base = qkv + (size_t)b * TT * C3;
    const int koff = h * HD;            // split order is (k, q, v)
    const int qoff = CC + h * HD;
    const int voff = 2 * CC + h * HD;

    // Load Q tile [64][64]
    #pragma unroll
    for (int i = 0; i < 16; i++) {
        int e = tid + i * 256;
        int r = e >> 6, d = e & 63;
        Qs[r * PAD + d] = base[(size_t)(qt * 64 + r) * C3 + qoff + d];
    }

    float o[4][4] = {};
    float m_run[4], l_run[4];
    #pragma unroll
    for (int i = 0; i < 4; i++) { m_run[i] = -1e30f; l_run[i] = 0.f; }

    const int r0 = ty * 4;   // S rows / O rows owned
    const int c0 = tx * 4;   // S cols owned; also O d-columns owned

    for (int j = 0; j <= qt; j++) {
        __syncthreads();  // protect K/V/Ps reuse (also publishes Q on iter 0)
        // Load K tile and V tile (V transposed)
        #pragma unroll
        for (int i = 0; i < 16; i++) {
            int e = tid + i * 256;
            int r = e >> 6, d = e & 63;
            size_t row = (size_t)(j * 64 + r) * C3;
            Ks[r * PAD + d] = base[row + koff + d];
            Vt[d * PAD + r] = base[row + voff + d];
        }
        __syncthreads();

        // S = Q @ K^T (owned 4x4), float4 over k
        float s[4][4] = {};
        #pragma unroll
        for (int k4 = 0; k4 < 16; k4++) {
            float4 q4[4], kk4[4];
            #pragma unroll
            for (int i = 0; i < 4; i++)
                q4[i] = *(const float4*)&Qs[(r0 + i) * PAD + k4 * 4];
            #pragma unroll
            for (int jj = 0; jj < 4; jj++)
                kk4[jj] = *(const float4*)&Ks[(c0 + jj) * PAD + k4 * 4];
            #pragma unroll
            for (int i = 0; i < 4; i++)
                #pragma unroll
                for (int jj = 0; jj < 4; jj++)
                    s[i][jj] += q4[i].x * kk4[jj].x + q4[i].y * kk4[jj].y +
                                q4[i].z * kk4[jj].z + q4[i].w * kk4[jj].w;
        }

        // Scale + causal mask (only the diagonal tile needs masking)
        const bool diag = (j == qt);
        #pragma unroll
        for (int i = 0; i < 4; i++)
            #pragma unroll
            for (int jj = 0; jj < 4; jj++) {
                s[i][jj] *= scale;
                if (diag && (c0 + jj) > (r0 + i)) s[i][jj] = -1e30f;
            }

        // Row max (partial -> smem -> full)
        #pragma unroll
        for (int i = 0; i < 4; i++) {
            float pm = fmaxf(fmaxf(s[i][0], s[i][1]), fmaxf(s[i][2], s[i][3]));
            red[(r0 + i) * 17 + tx] = pm;
        }
        __syncthreads();
        float m_new[4], alpha[4];
        #pragma unroll
        for (int i = 0; i < 4; i++) {
            float m = m_run[i];
            #pragma unroll
            for (int x = 0; x < 16; x++) m = fmaxf(m, red[(r0 + i) * 17 + x]);
            m_new[i] = m;
            alpha[i] = __expf(m_run[i] - m);
        }
        __syncthreads();  // before reusing red for sums

        // P = exp(S - m), partial row sums, write P tile
        #pragma unroll
        for (int i = 0; i < 4; i++) {
            float4 p4;
            p4.x = __expf(s[i][0] - m_new[i]);
            p4.y = __expf(s[i][1] - m_new[i]);
            p4.z = __expf(s[i][2] - m_new[i]);
            p4.w = __expf(s[i][3] - m_new[i]);
            *(float4*)&Ps[(r0 + i) * PAD + c0] = p4;
            red[(r0 + i) * 17 + tx] = p4.x + p4.y + p4.z + p4.w;
        }
        __syncthreads();

        // Finish softmax state, rescale O
        #pragma unroll
        for (int i = 0; i < 4; i++) {
            float ssum = 0.f;
            #pragma unroll
            for (int x = 0; x < 16; x++) ssum += red[(r0 + i) * 17 + x];
            l_run[i] = alpha[i] * l_run[i] + ssum;
            m_run[i] = m_new[i];
            #pragma unroll
            for (int jj = 0; jj < 4; jj++) o[i][jj] *= alpha[i];
        }

        // O += P @ V  (float4 over c, Vt is d-major so c is contiguous)
        #pragma unroll
        for (int c4 = 0; c4 < 16; c4++) {
            float4 p4[4], v4[4];
            #pragma unroll
            for (int i = 0; i < 4; i++)
                p4[i] = *(const float4*)&Ps[(r0 + i) * PAD + c4 * 4];
            #pragma unroll
            for (int jj = 0; jj < 4; jj++)
                v4[jj] = *(const float4*)&Vt[(c0 + jj) * PAD + c4 * 4];
            #pragma unroll
            for (int i = 0; i < 4; i++)
                #pragma unroll
                for (int jj = 0; jj < 4; jj++)
                    o[i][jj] += p4[i].x * v4[jj].x + p4[i].y * v4[jj].y +
                                p4[i].z * v4[jj].z + p4[i].w * v4[jj].w;
        }
    }

    // Write O / l to g_att: att[b, qt*64+r, h*64+d]
    #pragma unroll
    for (int i = 0; i < 4; i++) {
        float inv = 1.f / l_run[i];
        int t = qt * 64 + r0 + i;
        #pragma unroll
        for (int jj = 0; jj < 4; jj++)
            att[((size_t)b * TT + t) * CC + h * HD + c0 + jj] = o[i][jj] * inv;
    }
}

// ---------------------------------------------------------------------------
// Launch
// ---------------------------------------------------------------------------
extern "C" void kernel_launch(void* const* d_in, const int* in_sizes, int n_in,
                              void* d_out, int out_size) {
    const float* x      = (const float*)d_in[0];
    const float* W_attn = (const float*)d_in[1];
    const float* b_attn = (const float*)d_in[2];
    const float* W_proj = (const float*)d_in[3];
    const float* b_proj = (const float*)d_in[4];
    float* out = (float*)d_out;

    float* qkv; cudaGetSymbolAddress((void**)&qkv, g_qkv);
    float* att; cudaGetSymbolAddress((void**)&att, g_att);

    const int ATTN_SMEM = (4 * 64 * PAD + 64 * 17) * (int)sizeof(float); // 73984 B
    cudaFuncSetAttribute(flash_attn_kernel,
                         cudaFuncAttributeMaxDynamicSharedMemorySize, ATTN_SMEM);

    // 1) QKV = x @ W_attn + b_attn   : [8192,768] x [768,2304]
    dim3 g1(C3 / 64, (BB * TT) / 64);
    gemm_bias_kernel<<<g1, 256>>>(x, W_attn, b_attn, qkv, BB * TT, C3, CC);

    // 2) Flash attention (causal)
    dim3 g2(TT / 64, BB * NH);
    flash_attn_kernel<<<g2, 256, ATTN_SMEM>>>(qkv, att);

    // 3) out = att @ W_proj + b_proj : [8192,768] x [768,768]
    dim3 g3(CC / 64, (BB * TT) / 64);
    gemm_bias_kernel<<<g3, 256>>>(att, W_proj, b_proj, out, BB * TT, CC, CC);
}

// round 3
// speedup vs baseline: 5.0172x; 5.0172x over previous
#include <cuda_runtime.h>
#include <cstdint>

#define BB 2
#define TT 4096
#define CC 768
#define NH 12
#define HD 64
#define C3 (3*CC)

// Scratch (no cudaMalloc allowed)
__device__ float g_qkv[BB*TT*C3];   // [B,T,3C] : (k | q | v)
__device__ float g_att[BB*TT*CC];   // attention output before proj
__device__ float g_wt [C3*CC];      // W_attn^T  [2304][768]
__device__ float g_wtp[CC*CC];      // W_proj^T  [768][768]

__device__ __forceinline__ uint32_t f2tf32(float x){
    uint32_t u; asm("cvt.rna.tf32.f32 %0, %1;" : "=r"(u) : "f"(x)); return u;
}

__device__ __forceinline__ void mma_tf32(float* c, uint32_t a0, uint32_t a1,
                                         uint32_t a2, uint32_t a3,
                                         uint32_t b0, uint32_t b1){
    asm volatile(
        "mma.sync.aligned.m16n8k8.row.col.f32.tf32.tf32.f32 "
        "{%0,%1,%2,%3}, {%4,%5,%6,%7}, {%8,%9}, {%0,%1,%2,%3};"
        : "+f"(c[0]), "+f"(c[1]), "+f"(c[2]), "+f"(c[3])
        : "r"(a0), "r"(a1), "r"(a2), "r"(a3), "r"(b0), "r"(b1));
}

__device__ __forceinline__ uint32_t ldsf(const float* p){
    return __float_as_uint(*p);
}

// ---------------------------------------------------------------------------
// Weight transpose: W[K][N] -> Wt[N][K]
// ---------------------------------------------------------------------------
__global__ void transpose_kernel(const float* __restrict__ W, float* __restrict__ Wt,
                                 int K, int N){
    __shared__ float t[32][33];
    int n0 = blockIdx.x * 32, k0 = blockIdx.y * 32;
    int tx = threadIdx.x & 31, ty = threadIdx.x >> 5;
    for (int i = ty; i < 32; i += 8) t[i][tx] = W[(size_t)(k0 + i) * N + n0 + tx];
    __syncthreads();
    for (int i = ty; i < 32; i += 8) Wt[(size_t)(n0 + i) * K + k0 + tx] = t[tx][i];
}

// ---------------------------------------------------------------------------
// tf32 mma.sync GEMM: out[M,N] = A[M,K] @ Bt[N,K]^T + bias
// CTA tile 128x128, BK=32, 256 threads (8 warps, warp tile 32m x 64n),
// double-buffered smem, register prefetch. Rows padded to 36 floats so every
// fragment load is bank-conflict free.
// ---------------------------------------------------------------------------
#define GSTRIDE 36
#define GTILE   (128*GSTRIDE)
#define GEMM_SMEM (4*GTILE*4)   // As[2] + Bs[2], bytes

__global__ __launch_bounds__(256) void gemm_mma(const float* __restrict__ A,
                                                const float* __restrict__ Bt,
                                                const float* __restrict__ bias,
                                                float* __restrict__ out,
                                                int M, int N, int K){
    extern __shared__ float sm[];
    float* As = sm;              // [2][128][36]
    float* Bs = sm + 2*GTILE;    // [2][128][36]

    const int tid = threadIdx.x, wid = tid >> 5, lid = tid & 31;
    const int tq = lid >> 2, tr = lid & 3;          // quad row / lane-in-quad
    const int wm = (wid >> 1) * 32, wn = (wid & 1) * 64;
    const int m0 = blockIdx.y * 128, n0 = blockIdx.x * 128;
    const int KT = K / 32;
    const int lr = tid >> 3, lc = tid & 7;          // loader: row, float4-col

    float acc[2][8][4];
    #pragma unroll
    for (int i = 0; i < 2; i++)
        #pragma unroll
        for (int j = 0; j < 8; j++)
            #pragma unroll
            for (int e = 0; e < 4; e++) acc[i][j][e] = 0.f;

    float4 ra[4], rb[4];
    // prologue: load k-tile 0
    #pragma unroll
    for (int i = 0; i < 4; i++){
        ra[i] = *(const float4*)&A [(size_t)(m0 + lr + i*32) * K + lc*4];
        rb[i] = *(const float4*)&Bt[(size_t)(n0 + lr + i*32) * K + lc*4];
    }
    #pragma unroll
    for (int i = 0; i < 4; i++){
        float* pa = &As[(lr + i*32)*GSTRIDE + lc*4];
        float* pb = &Bs[(lr + i*32)*GSTRIDE + lc*4];
        pa[0]=__uint_as_float(f2tf32(ra[i].x)); pa[1]=__uint_as_float(f2tf32(ra[i].y));
        pa[2]=__uint_as_float(f2tf32(ra[i].z)); pa[3]=__uint_as_float(f2tf32(ra[i].w));
        pb[0]=__uint_as_float(f2tf32(rb[i].x)); pb[1]=__uint_as_float(f2tf32(rb[i].y));
        pb[2]=__uint_as_float(f2tf32(rb[i].z)); pb[3]=__uint_as_float(f2tf32(rb[i].w));
    }
    __syncthreads();

    for (int kt = 0; kt < KT; kt++){
        if (kt + 1 < KT){
            const int k0 = (kt + 1) * 32;
            #pragma unroll
            for (int i = 0; i < 4; i++){
                ra[i] = *(const float4*)&A [(size_t)(m0 + lr + i*32) * K + k0 + lc*4];
                rb[i] = *(const float4*)&Bt[(size_t)(n0 + lr + i*32) * K + k0 + lc*4];
            }
        }
        const float* Ab = As + (kt & 1) * GTILE;
        const float* Bb = Bs + (kt & 1) * GTILE;
        #pragma unroll
        for (int kk = 0; kk < 4; kk++){
            uint32_t a[2][4];
            #pragma unroll
            for (int mt = 0; mt < 2; mt++){
                const float* p = &Ab[(wm + mt*16 + tq)*GSTRIDE + kk*8 + tr];
                a[mt][0] = ldsf(p);
                a[mt][1] = ldsf(p + 8*GSTRIDE);
                a[mt][2] = ldsf(p + 4);
                a[mt][3] = ldsf(p + 8*GSTRIDE + 4);
            }
            #pragma unroll
            for (int nt = 0; nt < 8; nt++){
                const float* p = &Bb[(wn + nt*8 + tq)*GSTRIDE + kk*8 + tr];
                uint32_t b0 = ldsf(p), b1 = ldsf(p + 4);
                mma_tf32(acc[0][nt], a[0][0], a[0][1], a[0][2], a[0][3], b0, b1);
                mma_tf32(acc[1][nt], a[1][0], a[1][1], a[1][2], a[1][3], b0, b1);
            }
        }
        if (kt + 1 < KT){
            float* Aw = As + ((kt + 1) & 1) * GTILE;
            float* Bw = Bs + ((kt + 1) & 1) * GTILE;
            #pragma unroll
            for (int i = 0; i < 4; i++){
                float* pa = &Aw[(lr + i*32)*GSTRIDE + lc*4];
                float* pb = &Bw[(lr + i*32)*GSTRIDE + lc*4];
                pa[0]=__uint_as_float(f2tf32(ra[i].x)); pa[1]=__uint_as_float(f2tf32(ra[i].y));
                pa[2]=__uint_as_float(f2tf32(ra[i].z)); pa[3]=__uint_as_float(f2tf32(ra[i].w));
                pb[0]=__uint_as_float(f2tf32(rb[i].x)); pb[1]=__uint_as_float(f2tf32(rb[i].y));
                pb[2]=__uint_as_float(f2tf32(rb[i].z)); pb[3]=__uint_as_float(f2tf32(rb[i].w));
            }
        }
        __syncthreads();
    }

    // Epilogue: v2 stores with bias
    #pragma unroll
    for (int mt = 0; mt < 2; mt++){
        #pragma unroll
        for (int nt = 0; nt < 8; nt++){
            int col = n0 + wn + nt*8 + tr*2;
            float b0 = bias[col], b1 = bias[col + 1];
            int r0 = m0 + wm + mt*16 + tq;
            float2 v0 = make_float2(acc[mt][nt][0] + b0, acc[mt][nt][1] + b1);
            float2 v1 = make_float2(acc[mt][nt][2] + b0, acc[mt][nt][3] + b1);
            *(float2*)&out[(size_t)r0 * N + col] = v0;
            *(float2*)&out[(size_t)(r0 + 8) * N + col] = v1;
        }
    }
}

// ---------------------------------------------------------------------------
// tf32 mma.sync flash attention (causal).
// CTA: 128 q-rows, 256 threads (8 warps x 16 q-rows). Key tiles of 128.
// S = Q@K^T per warp (m16 x n128), softmax with quad shfl reductions,
// P staged through per-warp smem patch (C-frag -> A-frag), PV = P@V (m16 x n64).
// Row strides padded (72 / 132 floats) => conflict-free fragment loads.
// ---------------------------------------------------------------------------
#define KSTR 72
#define PSTR 132
#define QS_OFF 0
#define KS_OFF (128*KSTR)
#define VS_OFF (2*128*KSTR)
#define PS_OFF (3*128*KSTR)
#define ATTN_SMEM ((3*128*KSTR + 8*16*PSTR) * 4)

__global__ __launch_bounds__(256, 1) void attn_mma(const float* __restrict__ qkv,
                                                   float* __restrict__ att){
    extern __shared__ float sm[];
    const int tid = threadIdx.x, wid = tid >> 5, lid = tid & 31;
    const int tq = lid >> 2, tr = lid & 3;
    const int qt = blockIdx.x, bh = blockIdx.y;
    const int b = bh / NH, h = bh % NH;
    const int wq = wid * 16;

    const float* base = qkv + (size_t)b * TT * C3;
    const int koff = h * HD, qoff = CC + h * HD, voff = 2 * CC + h * HD; // (k,q,v)

    float* Qs = sm + QS_OFF;
    float* Ks = sm + KS_OFF;
    float* Vs = sm + VS_OFF;
    float* Ps = sm + PS_OFF + wid * 16 * PSTR;

    const int lr = tid >> 4, lc = tid & 15;   // loader: row(16 step), float4-col

    // Load Q tile [128][64] (tf32)
    #pragma unroll
    for (int i = 0; i < 8; i++){
        int r = lr + i * 16;
        float4 v = *(const float4*)&base[(size_t)(qt*128 + r) * C3 + qoff + lc*4];
        float* p = &Qs[r * KSTR + lc*4];
        p[0]=__uint_as_float(f2tf32(v.x)); p[1]=__uint_as_float(f2tf32(v.y));
        p[2]=__uint_as_float(f2tf32(v.z)); p[3]=__uint_as_float(f2tf32(v.w));
    }

    float oacc[8][4];
    #pragma unroll
    for (int i = 0; i < 8; i++)
        #pragma unroll
        for (int e = 0; e < 4; e++) oacc[i][e] = 0.f;
    float m0r = -1e30f, m1r = -1e30f, l0 = 0.f, l1 = 0.f;

    const int qg0 = qt*128 + wq + tq;       // global q row (first of pair)
    const int qg1 = qg0 + 8;

    for (int j = 0; j <= qt; j++){
        __syncthreads();   // prior tile's smem reads done (also publishes Q on j==0)
        // Load K,V tiles [128 key][64 d]
        #pragma unroll
        for (int i = 0; i < 8; i++){
            int r = lr + i * 16;
            const float* rp = &base[(size_t)(j*128 + r) * C3];
            float4 kv = *(const float4*)&rp[koff + lc*4];
            float4 vv = *(const float4*)&rp[voff + lc*4];
            float* pk = &Ks[r * KSTR + lc*4];
            float* pv = &Vs[r * KSTR + lc*4];
            pk[0]=__uint_as_float(f2tf32(kv.x)); pk[1]=__uint_as_float(f2tf32(kv.y));
            pk[2]=__uint_as_float(f2tf32(kv.z)); pk[3]=__uint_as_float(f2tf32(kv.w));
            pv[0]=__uint_as_float(f2tf32(vv.x)); pv[1]=__uint_as_float(f2tf32(vv.y));
            pv[2]=__uint_as_float(f2tf32(vv.z)); pv[3]=__uint_as_float(f2tf32(vv.w));
        }
        __syncthreads();

        // S = Q @ K^T : m16 x n128, k=64
        float sacc[16][4];
        #pragma unroll
        for (int nt = 0; nt < 16; nt++)
            #pragma unroll
            for (int e = 0; e < 4; e++) sacc[nt][e] = 0.f;
        #pragma unroll
        for (int kk = 0; kk < 8; kk++){
            const float* pa = &Qs[(wq + tq)*KSTR + kk*8 + tr];
            uint32_t a0 = ldsf(pa), a1 = ldsf(pa + 8*KSTR);
            uint32_t a2 = ldsf(pa + 4), a3 = ldsf(pa + 8*KSTR + 4);
            #pragma unroll
            for (int nt = 0; nt < 16; nt++){
                const float* pb = &Ks[(nt*8 + tq)*KSTR + kk*8 + tr];
                mma_tf32(sacc[nt], a0, a1, a2, a3, ldsf(pb), ldsf(pb + 4));
            }
        }

        // scale + causal mask
        const bool diag = (j == qt);
        #pragma unroll
        for (int nt = 0; nt < 16; nt++){
            #pragma unroll
            for (int e = 0; e < 4; e++){
                int key = j*128 + nt*8 + tr*2 + (e & 1);
                float s = sacc[nt][e] * 0.125f;
                int qg = (e < 2) ? qg0 : qg1;
                if (diag && key > qg) s = -1e30f;
                sacc[nt][e] = s;
            }
        }

        // row max (2 rows per thread), quad reduction
        float mx0 = -1e30f, mx1 = -1e30f;
        #pragma unroll
        for (int nt = 0; nt < 16; nt++){
            mx0 = fmaxf(mx0, fmaxf(sacc[nt][0], sacc[nt][1]));
            mx1 = fmaxf(mx1, fmaxf(sacc[nt][2], sacc[nt][3]));
        }
        mx0 = fmaxf(mx0, __shfl_xor_sync(0xffffffffu, mx0, 1));
        mx0 = fmaxf(mx0, __shfl_xor_sync(0xffffffffu, mx0, 2));
        mx1 = fmaxf(mx1, __shfl_xor_sync(0xffffffffu, mx1, 1));
        mx1 = fmaxf(mx1, __shfl_xor_sync(0xffffffffu, mx1, 2));
        mx0 = fmaxf(mx0, m0r); mx1 = fmaxf(mx1, m1r);
        float alpha0 = __expf(m0r - mx0), alpha1 = __expf(m1r - mx1);
        m0r = mx0; m1r = mx1;

        // P = exp(S - m), partial sums
        float s0 = 0.f, s1 = 0.f;
        #pragma unroll
        for (int nt = 0; nt < 16; nt++){
            sacc[nt][0] = __expf(sacc[nt][0] - mx0);
            sacc[nt][1] = __expf(sacc[nt][1] - mx0);
            sacc[nt][2] = __expf(sacc[nt][2] - mx1);
            sacc[nt][3] = __expf(sacc[nt][3] - mx1);
            s0 += sacc[nt][0] + sacc[nt][1];
            s1 += sacc[nt][2] + sacc[nt][3];
        }
        s0 += __shfl_xor_sync(0xffffffffu, s0, 1);
        s0 += __shfl_xor_sync(0xffffffffu, s0, 2);
        s1 += __shfl_xor_sync(0xffffffffu, s1, 1);
        s1 += __shfl_xor_sync(0xffffffffu, s1, 2);
        l0 = l0 * alpha0 + s0;
        l1 = l1 * alpha1 + s1;

        // Stage P (tf32) into per-warp smem patch: C-frag -> A-frag layout
        __syncwarp();
        #pragma unroll
        for (int nt = 0; nt < 16; nt++){
            float2 v0 = make_float2(__uint_as_float(f2tf32(sacc[nt][0])),
                                    __uint_as_float(f2tf32(sacc[nt][1])));
            float2 v1 = make_float2(__uint_as_float(f2tf32(sacc[nt][2])),
                                    __uint_as_float(f2tf32(sacc[nt][3])));
            *(float2*)&Ps[tq * PSTR + nt*8 + tr*2] = v0;
            *(float2*)&Ps[(tq + 8) * PSTR + nt*8 + tr*2] = v1;
        }
        __syncwarp();

        // rescale O
        #pragma unroll
        for (int nt = 0; nt < 8; nt++){
            oacc[nt][0] *= alpha0; oacc[nt][1] *= alpha0;
            oacc[nt][2] *= alpha1; oacc[nt][3] *= alpha1;
        }

        // O += P @ V : m16 x n64, k=128
        #pragma unroll
        for (int kk = 0; kk < 16; kk++){
            const float* pa = &Ps[tq * PSTR + kk*8 + tr];
            uint32_t a0 = ldsf(pa), a1 = ldsf(pa + 8*PSTR);
            uint32_t a2 = ldsf(pa + 4), a3 = ldsf(pa + 8*PSTR + 4);
            #pragma unroll
            for (int nt = 0; nt < 8; nt++){
                const float* pb = &Vs[(kk*8 + tr)*KSTR + nt*8 + tq];
                uint32_t b0 = ldsf(pb), b1 = ldsf(pb + 4*KSTR);
                mma_tf32(oacc[nt], a0, a1, a2, a3, b0, b1);
            }
        }
    }

    // Epilogue: normalize and store
    float inv0 = 1.f / l0, inv1 = 1.f / l1;
    const int row0 = qt*128 + wq + tq;
    #pragma unroll
    for (int nt = 0; nt < 8; nt++){
        int col = h*HD + nt*8 + tr*2;
        float2 v0 = make_float2(oacc[nt][0]*inv0, oacc[nt][1]*inv0);
        float2 v1 = make_float2(oacc[nt][2]*inv1, oacc[nt][3]*inv1);
        *(float2*)&att[((size_t)b*TT + row0) * CC + col] = v0;
        *(float2*)&att[((size_t)b*TT + row0 + 8) * CC + col] = v1;
    }
}

// ---------------------------------------------------------------------------
// Launch
// ---------------------------------------------------------------------------
extern "C" void kernel_launch(void* const* d_in, const int* in_sizes, int n_in,
                              void* d_out, int out_size){
    const float* x      = (const float*)d_in[0];
    const float* W_attn = (const float*)d_in[1];
    const float* b_attn = (const float*)d_in[2];
    const float* W_proj = (const float*)d_in[3];
    const float* b_proj = (const float*)d_in[4];
    float* out = (float*)d_out;

    float *qkv, *att, *wt, *wtp;
    cudaGetSymbolAddress((void**)&qkv, g_qkv);
    cudaGetSymbolAddress((void**)&att, g_att);
    cudaGetSymbolAddress((void**)&wt,  g_wt);
    cudaGetSymbolAddress((void**)&wtp, g_wtp);

    cudaFuncSetAttribute(gemm_mma, cudaFuncAttributeMaxDynamicSharedMemorySize, GEMM_SMEM);
    cudaFuncSetAttribute(attn_mma, cudaFuncAttributeMaxDynamicSharedMemorySize, ATTN_SMEM);

    // Transpose weights once: W[K][N] -> Wt[N][K]
    transpose_kernel<<<dim3(C3/32, CC/32), 256>>>(W_attn, wt, CC, C3);
    transpose_kernel<<<dim3(CC/32, CC/32), 256>>>(W_proj, wtp, CC, CC);

    // 1) QKV = x @ W_attn + b_attn   [8192,768] x [768,2304]
    gemm_mma<<<dim3(C3/128, (BB*TT)/128), 256, GEMM_SMEM>>>(x, wt, b_attn, qkv, BB*TT, C3, CC);

    // 2) Flash attention (causal)
    attn_mma<<<dim3(TT/128, BB*NH), 256, ATTN_SMEM>>>(qkv, att);

    // 3) out = att @ W_proj + b_proj  [8192,768] x [768,768]
    gemm_mma<<<dim3(CC/128, (BB*TT)/128), 256, GEMM_SMEM>>>(att, wtp, b_proj, out, BB*TT, CC, CC);
}